// round 16
// baseline (speedup 1.0000x reference)
#include <cuda_runtime.h>
#include <cstdint>
#include <math.h>

// RMAC: x [64, 2048, 16, 16] f32 -> out [64, 14*2048] f32, L2-normalized per batch.
// Regions: L1 1x(16x16), L2 4x(10x10, starts {0,4}), L3 9x(8x8, starts {0,3,6}).
// Single persistent kernel. Key trick: pooled outputs are RETAINED IN REGISTERS
// across a grid barrier and written to gmem exactly once, pre-scaled by 1/norm.
// Traffic: 128 MiB read (x) + 14 MiB write (out) + tiny partials.

#define B_TOT   64
#define C_TOT   2048
#define NREG    14
#define OUT_PER_B (NREG * C_TOT)        // 28672

#define CHB     16                      // channels per tile
#define TPB     128                     // threads per block
#define TILE_F4 (CHB * 64)              // 1024 float4 per tile (16 KiB)
#define TILE_W  (CHB * 256)             // 4096 floats
#define NTILES  (B_TOT * (C_TOT / CHB)) // 8192
#define GRID_MAIN 740                   // 5 blocks/SM x 148 SMs, fully co-resident
#define TPT     12                      // max tiles per block: ceil(8192/740)
#define RSTRIDE 144                     // phase-3 smem stride (conflict-free combine)

__device__ float g_part[NTILES];        // per-tile sum of squares
__device__ float g_inv[B_TOT];          // per-batch 1/norm
__device__ unsigned g_cnt = 0;          // barrier arrivals (returns to 0 each pass)
__device__ unsigned g_gen = 0;          // barrier generation (monotonic across replays)

__device__ __forceinline__ void cp16(unsigned int s, const void* g) {
    asm volatile("cp.async.cg.shared.global [%0], [%1], 16;" :: "r"(s), "l"(g) : "memory");
}
__device__ __forceinline__ void cp_commit() {
    asm volatile("cp.async.commit_group;" ::: "memory");
}
__device__ __forceinline__ void cp_wait1() {
    asm volatile("cp.async.wait_group 1;" ::: "memory");
}
__device__ __forceinline__ void cp_wait0() {
    asm volatile("cp.async.wait_group 0;" ::: "memory");
}

// Grid-wide barrier. Safe only because all GRID_MAIN blocks are co-resident
// (5/SM by __launch_bounds__ + 33 KiB smem; 5*148 = 740 = GRID_MAIN).
__device__ __forceinline__ void grid_barrier(int t) {
    __syncthreads();
    if (t == 0) {
        __threadfence();
        unsigned my = *((volatile unsigned*)&g_gen);
        unsigned old = atomicAdd(&g_cnt, 1);
        if (old == GRID_MAIN - 1) {
            g_cnt = 0;
            __threadfence();
            atomicAdd(&g_gen, 1);
        } else {
            while (*((volatile unsigned*)&g_gen) == my) { }
            __threadfence();
        }
    }
    __syncthreads();
}

__global__ __launch_bounds__(TPB, 5) void rmac_fused_kernel(
    const float* __restrict__ x, float* __restrict__ out)
{
    __shared__ __align__(16) float sm[2 * TILE_W];   // 32 KiB, double buffer
    const int t = threadIdx.x;
    const unsigned int sbase = (unsigned int)__cvta_generic_to_shared(sm);

    auto issue = [&](int tile, int p) {
        const float4* __restrict__ gv =
            reinterpret_cast<const float4*>(x) + (size_t)tile * TILE_F4;
        const unsigned int bb = sbase + (unsigned int)p * (TILE_W * 4);
        #pragma unroll
        for (int i = 0; i < TILE_F4 / TPB; i++) {    // 8 x cp.async per thread
            const int q  = i * TPB + t;
            const int ch = q >> 6;
            const int qw = q & 63;
            cp16(bb + (unsigned int)((ch * 64 + (qw ^ (ch & 7))) * 16), gv + q);
        }
    };

    const int t0 = blockIdx.x;
    if (t0 < NTILES) issue(t0, 0);
    cp_commit();
    if (t0 + GRID_MAIN < NTILES) issue(t0 + GRID_MAIN, 1);
    cp_commit();

    const int ch     = t & (CHB - 1);
    const int rchunk = t >> 4;
    const int sw     = ch & 7;

    // output coords for this thread: idx = t (region rA) and idx = t+128 (rB)
    const int rA = t >> 4,          ccA = t & 15;          // rA in 0..7
    const int rB = (t + 128) >> 4,  ccB = t & 15;          // rB in 8..13 (t<96)
    const float invA = (rA == 0) ? (1.0f/256.0f) : (rA < 5) ? (1.0f/100.0f) : (1.0f/64.0f);

    float keepA[TPT];                 // retained outputs (registers)
    float keepB[TPT];                 // valid only for t < 96

    int j = 0;
    for (int tile = t0; tile < NTILES; tile += GRID_MAIN, j++) {
        float* cur = sm + (j & 1) * TILE_W;
        const float4* __restrict__ cv = reinterpret_cast<const float4*>(cur) + ch * 64;

        cp_wait1();
        __syncthreads();

        // ---- pool 2 rows of one channel ----
        float acc[NREG];
        #pragma unroll
        for (int r = 0; r < NREG; r++) acc[r] = 0.0f;

        #pragma unroll
        for (int rr = 0; rr < 2; rr++) {
            const int h = rchunk * 2 + rr;
            float rowv[16];
            #pragma unroll
            for (int jj = 0; jj < 4; jj++) {
                const float4 v = cv[(h * 4 + jj) ^ sw];   // LDS.128, conflict-free
                rowv[jj*4+0] = v.x; rowv[jj*4+1] = v.y;
                rowv[jj*4+2] = v.z; rowv[jj*4+3] = v.w;
            }
            float pre[17];
            pre[0] = 0.0f;
            float p = 0.0f;
            #pragma unroll
            for (int q = 0; q < 16; q++) { p += rowv[q]; pre[q + 1] = p; }

            const float s16  = pre[16];
            const float c10a = pre[10];
            const float c10b = pre[14] - pre[4];
            const float c8a  = pre[8];
            const float c8b  = pre[11] - pre[3];
            const float c8c  = pre[14] - pre[6];

            acc[0] += s16;
            if (h < 10)           { acc[1]  += c10a; acc[2]  += c10b; }
            if (h >= 4 && h < 14) { acc[3]  += c10a; acc[4]  += c10b; }
            if (h < 8)            { acc[5]  += c8a;  acc[6]  += c8b;  acc[7]  += c8c; }
            if (h >= 3 && h < 11) { acc[8]  += c8a;  acc[9]  += c8b;  acc[10] += c8c; }
            if (h >= 6 && h < 14) { acc[11] += c8a;  acc[12] += c8b;  acc[13] += c8c; }
        }
        __syncthreads();

        // ---- combine 8 row-chunk partials per channel via smem (reuse cur) ----
        float* red = cur;                       // 14 * 144 = 2016 floats
        #pragma unroll
        for (int r = 0; r < NREG; r++) red[r * RSTRIDE + t] = acc[r];
        __syncthreads();

        float ss = 0.0f;
        {
            float vA = 0.0f;
            #pragma unroll
            for (int k = 0; k < 8; k++) vA += red[rA * RSTRIDE + ccA + 16 * k];
            vA *= invA;
            keepA[j] = vA;
            ss += vA * vA;
        }
        if (t < 96) {
            float vB = 0.0f;
            #pragma unroll
            for (int k = 0; k < 8; k++) vB += red[rB * RSTRIDE + ccB + 16 * k];
            vB *= (1.0f / 64.0f);               // rB >= 8 -> always an 8x8 region
            keepB[j] = vB;
            ss += vB * vB;
        }

        // block-reduce ss -> g_part[tile] (plain store, no atomics)
        #pragma unroll
        for (int o = 16; o > 0; o >>= 1)
            ss += __shfl_down_sync(0xffffffffu, ss, o);
        float* wsum = cur + 2048;
        if ((t & 31) == 0) wsum[t >> 5] = ss;
        __syncthreads();
        if (t == 0) g_part[tile] = wsum[0] + wsum[1] + wsum[2] + wsum[3];
        __syncthreads();

        const int nt = tile + 2 * GRID_MAIN;
        if (nt < NTILES) issue(nt, j & 1);
        cp_commit();
    }

    // ---- drain, then compute per-batch inverse norms ----
    cp_wait0();
    grid_barrier(t);       // all g_part writes visible chip-wide

    if (blockIdx.x < B_TOT) {
        float v = g_part[blockIdx.x * 128 + t];      // one partial per thread
        #pragma unroll
        for (int o = 16; o > 0; o >>= 1)
            v += __shfl_down_sync(0xffffffffu, v, o);
        if ((t & 31) == 0) sm[t >> 5] = v;
        __syncthreads();
        if (t == 0)
            g_inv[blockIdx.x] = 1.0f / fmaxf(sqrtf(sm[0] + sm[1] + sm[2] + sm[3]), 1e-12f);
    }
    grid_barrier(t);       // g_inv visible

    // ---- single scaled write of the retained outputs (only out write at all) ----
    #pragma unroll
    for (int jj = 0; jj < TPT; jj++) {
        const int tile = t0 + jj * GRID_MAIN;
        if (tile < NTILES) {
            const int b  = tile >> 7;
            const int c0 = (tile & 127) * CHB;
            const float inv = g_inv[b];
            float* __restrict__ outb = out + (size_t)b * OUT_PER_B;
            outb[rA * C_TOT + c0 + ccA] = keepA[jj] * inv;
            if (t < 96)
                outb[rB * C_TOT + c0 + ccB] = keepB[jj] * inv;
        }
    }
}

extern "C" void kernel_launch(void* const* d_in, const int* in_sizes, int n_in,
                              void* d_out, int out_size) {
    (void)in_sizes; (void)n_in; (void)out_size;
    const float* x = (const float*)d_in[0];
    float* out = (float*)d_out;

    rmac_fused_kernel<<<GRID_MAIN, TPB>>>(x, out);
}